// round 8
// baseline (speedup 1.0000x reference)
#include <cuda_runtime.h>
#include <cstdint>

#define NCTA      4
#define BC        4      // batch elements per cluster
#define HID       128
#define NTHREADS  512
#define NWIN      252    // prediction steps = T - WS
#define TT        256    // trajectory length
#define PADH      132    // padded row stride (float4-phase conflict-free)
#define LROWS     128    // local gate rows per CTA (32 units x 4 gates)

struct Smem {
    float Wih1s[LROWS * PADH];
    float Whh1s[LROWS * PADH];
    float Whh0s[LROWS * PADH];
    float Wih0s[LROWS * 4];
    float h0buf[2][BC * PADH];   // ping-pong h buffers (cluster-shared)
    float h1buf[2][BC * PADH];
    float gates1[BC * PADH];
    float gates0[BC * PADH];
    float xin[4 * BC * 4];       // [t][b][f(pad4)]
    float b0s[LROWS];
    float b1s[LROWS];
    float Wl[2 * HID];
    float winbuf[BC * 4 * 2];    // [b][j][o] last 4 predictions
    float pred[BC * 2];
    float bl[2];
};

#define FFMA2(acc, w, h) \
    asm("fma.rn.f32x2 %0, %1, %2, %0;" : "+l"(acc) : "l"(w), "l"(h))

__device__ __forceinline__ unsigned long long pk2(float lo, float hi) {
    unsigned long long r;
    asm("mov.b64 %0, {%1, %2};" : "=l"(r) : "f"(lo), "f"(hi));
    return r;
}
__device__ __forceinline__ float hsum2(unsigned long long a) {
    float lo, hi;
    asm("mov.b64 {%0, %1}, %2;" : "=f"(lo), "=f"(hi) : "l"(a));
    return lo + hi;
}

__device__ __forceinline__ void cluster_sync_all() {
    asm volatile("barrier.cluster.arrive.aligned;" ::: "memory");
    asm volatile("barrier.cluster.wait.aligned;" ::: "memory");
}

__device__ __forceinline__ float sigf(float x) {
    return 1.0f / (1.0f + __expf(-x));
}

// broadcast one float to the same smem slot in all 4 cluster CTAs
__device__ __forceinline__ void push4(float v, float* dst) {
    uint32_t la = (uint32_t)__cvta_generic_to_shared(dst);
#pragma unroll
    for (int rr = 0; rr < NCTA; rr++) {
        uint32_t ra;
        asm volatile("mapa.shared::cluster.u32 %0, %1, %2;"
                     : "=r"(ra) : "r"(la), "r"(rr));
        asm volatile("st.shared::cluster.f32 [%0], %1;"
                     :: "r"(ra), "f"(v) : "memory");
    }
}

// gates -> activations for one (b,u); c lives in a register of the owner thread
__device__ __forceinline__ float act_one(const float* gates, float& creg,
                                         bool first, int b, int u) {
    const float* g = gates + b * PADH;
    float vi = sigf(g[u]);
    float vf = sigf(g[32 + u]);
    float vg = tanhf(g[64 + u]);
    float vo = sigf(g[96 + u]);
    float cc = vi * vg;
    if (!first) cc = fmaf(vf, creg, cc);
    creg = cc;
    return vo * tanhf(cc);
}

// Combined-stage GEMV for one (row r, batch b):
//   gates1[r] = b1 + Wih1[r]·h0  (+ Whh1[r]·h1 if has_hh1)
//   gates0[r] = b0 + Wih0[r]·x[t_next] + Whh0[r]·h0   (if has_g0)
__device__ __forceinline__ void stage_gemv(Smem& s,
                                           const float* h0r, const float* h1r,
                                           int r, int b, int t_next,
                                           bool has_hh1, bool has_g0) {
    unsigned long long Aih1 = pk2(s.b1s[r], 0.0f);
    unsigned long long Ahh1 = pk2(0.0f, 0.0f);
    unsigned long long Ahh0 = 0ull;
    if (has_g0) {
        const float* x  = &s.xin[(t_next * 4 + b) * 4];
        const float* wx = &s.Wih0s[r * 4];
        float a = s.b0s[r];
        a = fmaf(wx[0], x[0], fmaf(wx[1], x[1], fmaf(wx[2], x[2], a)));
        Ahh0 = pk2(a, 0.0f);
    }
    const ulonglong2* pih1 = reinterpret_cast<const ulonglong2*>(&s.Wih1s[r * PADH]);
    const ulonglong2* phh1 = reinterpret_cast<const ulonglong2*>(&s.Whh1s[r * PADH]);
    const ulonglong2* phh0 = reinterpret_cast<const ulonglong2*>(&s.Whh0s[r * PADH]);
    const ulonglong2* p0   = reinterpret_cast<const ulonglong2*>(h0r + b * PADH);
    const ulonglong2* p1   = reinterpret_cast<const ulonglong2*>(h1r + b * PADH);
#pragma unroll
    for (int k = 0; k < HID / 4; k++) {
        ulonglong2 hv = p0[k];
        ulonglong2 wa = pih1[k];
        FFMA2(Aih1, wa.x, hv.x);
        FFMA2(Aih1, wa.y, hv.y);
        if (has_g0) {
            ulonglong2 wc = phh0[k];
            FFMA2(Ahh0, wc.x, hv.x);
            FFMA2(Ahh0, wc.y, hv.y);
        }
        if (has_hh1) {
            ulonglong2 h1v = p1[k];
            ulonglong2 wb  = phh1[k];
            FFMA2(Ahh1, wb.x, h1v.x);
            FFMA2(Ahh1, wb.y, h1v.y);
        }
    }
    s.gates1[b * PADH + r] = hsum2(Aih1) + hsum2(Ahh1);
    if (has_g0) s.gates0[b * PADH + r] = hsum2(Ahh0);
}

extern __shared__ float smem_raw[];

__global__ void __cluster_dims__(NCTA, 1, 1) __launch_bounds__(NTHREADS, 1)
lstm_kernel(const float* __restrict__ traj,
            const float* __restrict__ Wih0, const float* __restrict__ Whh0,
            const float* __restrict__ bih0, const float* __restrict__ bhh0,
            const float* __restrict__ Wih1, const float* __restrict__ Whh1,
            const float* __restrict__ bih1, const float* __restrict__ bhh1,
            const float* __restrict__ Wl,   const float* __restrict__ bl,
            float* __restrict__ out) {
    Smem& s = *reinterpret_cast<Smem*>(smem_raw);
    const int tid = threadIdx.x;
    uint32_t rank;
    asm("mov.u32 %0, %%cluster_ctarank;" : "=r"(rank));
    const int cluster = blockIdx.x / NCTA;
    const int gb0 = cluster * BC;

    // ---- load weight slices: local row lr = g*32+u <-> global row g*128 + rank*32 + u
    for (int i = tid; i < LROWS * HID; i += NTHREADS) {
        int lr = i / HID, k = i % HID;
        int g = lr >> 5, u = lr & 31;
        int gr = g * 128 + (int)rank * 32 + u;
        s.Whh0s[lr * PADH + k] = Whh0[gr * HID + k];
        s.Wih1s[lr * PADH + k] = Wih1[gr * HID + k];
        s.Whh1s[lr * PADH + k] = Whh1[gr * HID + k];
    }
    for (int lr = tid; lr < LROWS; lr += NTHREADS) {
        int g = lr >> 5, u = lr & 31;
        int gr = g * 128 + (int)rank * 32 + u;
        s.Wih0s[lr * 4 + 0] = Wih0[gr * 3 + 0];
        s.Wih0s[lr * 4 + 1] = Wih0[gr * 3 + 1];
        s.Wih0s[lr * 4 + 2] = Wih0[gr * 3 + 2];
        s.Wih0s[lr * 4 + 3] = 0.0f;
        s.b0s[lr] = bih0[gr] + bhh0[gr];
        s.b1s[lr] = bih1[gr] + bhh1[gr];
    }
    for (int i = tid; i < 2 * HID; i += NTHREADS) s.Wl[i] = Wl[i];
    if (tid < 2) s.bl[tid] = bl[tid];
    __syncthreads();
    cluster_sync_all();

    const int r    = tid >> 2;   // 0..127 : one gate row per thread
    const int b_of = tid & 3;    // batch within cluster

    int pw = 0;                  // ping-pong parity (identical across CTAs)
    float c0reg = 0.0f, c1reg = 0.0f, h0last = 0.0f, h1last = 0.0f;

    for (int w = 0; w < NWIN; w++) {
        // ---- build window inputs xin[t][b][f] for t=0..3
        if (tid < 64) {
            int t = tid >> 4, b = (tid >> 2) & 3, f = tid & 3;
            if (f < 3) {
                int gb = gb0 + b;
                float v;
                if (w == 0) {
                    v = traj[(gb * TT + t) * 3 + f];
                } else if (w < 4) {
                    if (t < 3) v = traj[(gb * TT + (w + t)) * 3 + f];
                    else v = (f == 0) ? traj[(gb * TT + (4 + w)) * 3 + 0]
                                      : s.winbuf[(b * 4 + 3) * 2 + (f - 1)];
                } else {
                    v = (f < 2) ? s.winbuf[(b * 4 + t) * 2 + f]
                                : traj[(gb * TT + (w + t)) * 3 + 0];
                }
                s.xin[(t * 4 + b) * 4 + f] = v;
            }
        }
        __syncthreads();

        // ---- s0: layer-0 gates at t=0 (x-only)
        {
            const float* x  = &s.xin[(0 * 4 + b_of) * 4];
            const float* wx = &s.Wih0s[r * 4];
            float a = s.b0s[r];
            a = fmaf(wx[0], x[0], fmaf(wx[1], x[1], fmaf(wx[2], x[2], a)));
            s.gates0[b_of * PADH + r] = a;
        }
        __syncthreads();
        if (tid >= 128 && tid < 256) {
            int t2 = tid - 128, ab = t2 >> 5, u = t2 & 31;
            h0last = act_one(s.gates0, c0reg, true, ab, u);
            push4(h0last, &s.h0buf[pw ^ 1][ab * PADH + (int)rank * 32 + u]);
        }
        cluster_sync_all();
        pw ^= 1;

        // ---- combined stages: produce h1[st] and h0[st+1] per sync
#pragma unroll
        for (int st = 0; st < 3; st++) {
            stage_gemv(s, s.h0buf[pw], s.h1buf[pw], r, b_of, st + 1, st > 0, true);
            __syncthreads();
            if (tid < 128) {
                int ab = tid >> 5, u = tid & 31;
                h1last = act_one(s.gates1, c1reg, st == 0, ab, u);
                push4(h1last, &s.h1buf[pw ^ 1][ab * PADH + (int)rank * 32 + u]);
            } else if (tid < 256) {
                int t2 = tid - 128, ab = t2 >> 5, u = t2 & 31;
                h0last = act_one(s.gates0, c0reg, false, ab, u);
                push4(h0last, &s.h0buf[pw ^ 1][ab * PADH + (int)rank * 32 + u]);
            }
            cluster_sync_all();
            pw ^= 1;
        }

        // ---- s4: last layer-1 step (t=3)
        stage_gemv(s, s.h0buf[pw], s.h1buf[pw], r, b_of, 0, true, false);
        __syncthreads();
        if (tid < 128) {
            int ab = tid >> 5, u = tid & 31;
            h1last = act_one(s.gates1, c1reg, false, ab, u);
            push4(h1last, &s.h1buf[pw ^ 1][ab * PADH + (int)rank * 32 + u]);
        }
        cluster_sync_all();
        pw ^= 1;

        // ---- head: pred[b][o] = Wl[o,:]·h1[b,:] + bl[o]  (8 warps, warp reduce)
        if (tid < 256) {
            int wid = tid >> 5, lane = tid & 31;
            int b = wid >> 1, o = wid & 1;
            const float4* wl4 = reinterpret_cast<const float4*>(&s.Wl[o * HID]);
            const float4* h4  = reinterpret_cast<const float4*>(&s.h1buf[pw][b * PADH]);
            float4 a = wl4[lane], hh = h4[lane];
            float p = a.x * hh.x + a.y * hh.y + a.z * hh.z + a.w * hh.w;
            p += __shfl_xor_sync(0xFFFFFFFFu, p, 16);
            p += __shfl_xor_sync(0xFFFFFFFFu, p, 8);
            p += __shfl_xor_sync(0xFFFFFFFFu, p, 4);
            p += __shfl_xor_sync(0xFFFFFFFFu, p, 2);
            p += __shfl_xor_sync(0xFFFFFFFFu, p, 1);
            if (lane == 0) s.pred[b * 2 + o] = p + s.bl[o];
        }
        __syncthreads();
        if (tid < 8) {
            int b = tid >> 1, o = tid & 1;
            int gb = gb0 + b;
            float base = (w < 4) ? traj[(gb * TT + 3 + w) * 3 + 1 + o]
                                 : s.winbuf[(b * 4 + 3) * 2 + o];
            float pn = base + s.pred[b * 2 + o];
            float t1 = s.winbuf[(b * 4 + 1) * 2 + o];
            float t2 = s.winbuf[(b * 4 + 2) * 2 + o];
            float t3 = s.winbuf[(b * 4 + 3) * 2 + o];
            s.winbuf[(b * 4 + 0) * 2 + o] = t1;
            s.winbuf[(b * 4 + 1) * 2 + o] = t2;
            s.winbuf[(b * 4 + 2) * 2 + o] = t3;
            s.winbuf[(b * 4 + 3) * 2 + o] = pn;
            if (rank == 0) out[(gb * NWIN + w) * 2 + o] = pn;
        }
        __syncthreads();
    }

    // ---- final hidden/cell states from owner-thread registers
    const int OFF_H = 128 * NWIN * 2;          // 64512
    const int OFF_C = OFF_H + 2 * 128 * HID;   // 97280
    if (tid < 128) {
        int b = tid >> 5, u = tid & 31;
        int j = (int)rank * 32 + u, gb = gb0 + b;
        out[OFF_H + 1 * 128 * HID + gb * HID + j] = h1last;
        out[OFF_C + 1 * 128 * HID + gb * HID + j] = c1reg;
    } else if (tid < 256) {
        int t2 = tid - 128, b = t2 >> 5, u = t2 & 31;
        int j = (int)rank * 32 + u, gb = gb0 + b;
        out[OFF_H + 0 * 128 * HID + gb * HID + j] = h0last;
        out[OFF_C + 0 * 128 * HID + gb * HID + j] = c0reg;
    }
}

extern "C" void kernel_launch(void* const* d_in, const int* in_sizes, int n_in,
                              void* d_out, int out_size) {
    const float* traj = (const float*)d_in[0];
    const float* Wih0 = (const float*)d_in[1];
    const float* Whh0 = (const float*)d_in[2];
    const float* bih0 = (const float*)d_in[3];
    const float* bhh0 = (const float*)d_in[4];
    const float* Wih1 = (const float*)d_in[5];
    const float* Whh1 = (const float*)d_in[6];
    const float* bih1 = (const float*)d_in[7];
    const float* bhh1 = (const float*)d_in[8];
    const float* Wl   = (const float*)d_in[9];
    const float* bl   = (const float*)d_in[10];
    float* out = (float*)d_out;

    int smem = (int)sizeof(Smem);
    cudaFuncSetAttribute(lstm_kernel, cudaFuncAttributeMaxDynamicSharedMemorySize, smem);
    lstm_kernel<<<128, NTHREADS, smem>>>(traj, Wih0, Whh0, bih0, bhh0,
                                         Wih1, Whh1, bih1, bhh1, Wl, bl, out);
}

// round 9
// speedup vs baseline: 1.0023x; 1.0023x over previous
#include <cuda_runtime.h>
#include <cstdint>

#define NCTA      4
#define BC        4      // batch elements per cluster
#define HID       128
#define NTHREADS  512
#define NWIN      252    // prediction steps = T - WS
#define TT        256    // trajectory length
#define PADH      132    // padded row stride (float4-phase conflict-free)
#define LROWS     128    // local gate rows per CTA (32 units x 4 gates)

struct Smem {
    float Wih1s[LROWS * PADH];
    float Whh1s[LROWS * PADH];
    float Whh0s[LROWS * PADH];
    float Wih0s[LROWS * 4];
    float h0buf[2][BC * PADH];   // ping-pong h buffers (cluster-shared)
    float h1buf[2][BC * PADH];
    float gates1[BC * PADH];
    float gates0[BC * PADH];
    float xin[4 * BC * 4];       // [t][b][f(pad4)]
    float b0s[LROWS];
    float b1s[LROWS];
    float Wl[2 * HID];
    float winbuf[BC * 4 * 2];    // [b][j][o] last 4 predictions
    float pred[BC * 2];
    float bl[2];
};

#define FFMA2(acc, w, h) \
    asm("fma.rn.f32x2 %0, %1, %2, %0;" : "+l"(acc) : "l"(w), "l"(h))

__device__ __forceinline__ unsigned long long pk2(float lo, float hi) {
    unsigned long long r;
    asm("mov.b64 %0, {%1, %2};" : "=l"(r) : "f"(lo), "f"(hi));
    return r;
}
__device__ __forceinline__ float hsum2(unsigned long long a) {
    float lo, hi;
    asm("mov.b64 {%0, %1}, %2;" : "=f"(lo), "=f"(hi) : "l"(a));
    return lo + hi;
}

__device__ __forceinline__ void cluster_sync_all() {
    asm volatile("barrier.cluster.arrive.aligned;" ::: "memory");
    asm volatile("barrier.cluster.wait.aligned;" ::: "memory");
}

__device__ __forceinline__ float sigf(float x) {
    return 1.0f / (1.0f + __expf(-x));
}

// broadcast one float to the same smem slot in all 4 cluster CTAs
__device__ __forceinline__ void push4(float v, float* dst) {
    uint32_t la = (uint32_t)__cvta_generic_to_shared(dst);
#pragma unroll
    for (int rr = 0; rr < NCTA; rr++) {
        uint32_t ra;
        asm volatile("mapa.shared::cluster.u32 %0, %1, %2;"
                     : "=r"(ra) : "r"(la), "r"(rr));
        asm volatile("st.shared::cluster.f32 [%0], %1;"
                     :: "r"(ra), "f"(v) : "memory");
    }
}

// gates -> activations for one (b,u); c lives in a register of the owner thread
__device__ __forceinline__ float act_one(const float* gates, float& creg,
                                         bool first, int b, int u) {
    const float* g = gates + b * PADH;
    float vi = sigf(g[u]);
    float vf = sigf(g[32 + u]);
    float vg = tanhf(g[64 + u]);
    float vo = sigf(g[96 + u]);
    float cc = vi * vg;
    if (!first) cc = fmaf(vf, creg, cc);
    creg = cc;
    return vo * tanhf(cc);
}

// Combined-stage GEMV for one (row r, batch b):
//   gates1[r] = b1 + Wih1[r]·h0  (+ Whh1[r]·h1 if has_hh1)
//   gates0[r] = b0 + Wih0[r]·x[t_next] + Whh0[r]·h0   (if has_g0)
__device__ __forceinline__ void stage_gemv(Smem& s,
                                           const float* h0r, const float* h1r,
                                           int r, int b, int t_next,
                                           bool has_hh1, bool has_g0) {
    unsigned long long Aih1 = pk2(s.b1s[r], 0.0f);
    unsigned long long Ahh1 = pk2(0.0f, 0.0f);
    unsigned long long Ahh0 = 0ull;
    if (has_g0) {
        const float* x  = &s.xin[(t_next * 4 + b) * 4];
        const float* wx = &s.Wih0s[r * 4];
        float a = s.b0s[r];
        a = fmaf(wx[0], x[0], fmaf(wx[1], x[1], fmaf(wx[2], x[2], a)));
        Ahh0 = pk2(a, 0.0f);
    }
    const ulonglong2* pih1 = reinterpret_cast<const ulonglong2*>(&s.Wih1s[r * PADH]);
    const ulonglong2* phh1 = reinterpret_cast<const ulonglong2*>(&s.Whh1s[r * PADH]);
    const ulonglong2* phh0 = reinterpret_cast<const ulonglong2*>(&s.Whh0s[r * PADH]);
    const ulonglong2* p0   = reinterpret_cast<const ulonglong2*>(h0r + b * PADH);
    const ulonglong2* p1   = reinterpret_cast<const ulonglong2*>(h1r + b * PADH);
#pragma unroll
    for (int k = 0; k < HID / 4; k++) {
        ulonglong2 hv = p0[k];
        ulonglong2 wa = pih1[k];
        FFMA2(Aih1, wa.x, hv.x);
        FFMA2(Aih1, wa.y, hv.y);
        if (has_g0) {
            ulonglong2 wc = phh0[k];
            FFMA2(Ahh0, wc.x, hv.x);
            FFMA2(Ahh0, wc.y, hv.y);
        }
        if (has_hh1) {
            ulonglong2 h1v = p1[k];
            ulonglong2 wb  = phh1[k];
            FFMA2(Ahh1, wb.x, h1v.x);
            FFMA2(Ahh1, wb.y, h1v.y);
        }
    }
    s.gates1[b * PADH + r] = hsum2(Aih1) + hsum2(Ahh1);
    if (has_g0) s.gates0[b * PADH + r] = hsum2(Ahh0);
}

extern __shared__ float smem_raw[];

__global__ void __cluster_dims__(NCTA, 1, 1) __launch_bounds__(NTHREADS, 1)
lstm_kernel(const float* __restrict__ traj,
            const float* __restrict__ Wih0, const float* __restrict__ Whh0,
            const float* __restrict__ bih0, const float* __restrict__ bhh0,
            const float* __restrict__ Wih1, const float* __restrict__ Whh1,
            const float* __restrict__ bih1, const float* __restrict__ bhh1,
            const float* __restrict__ Wl,   const float* __restrict__ bl,
            float* __restrict__ out) {
    Smem& s = *reinterpret_cast<Smem*>(smem_raw);
    const int tid = threadIdx.x;
    uint32_t rank;
    asm("mov.u32 %0, %%cluster_ctarank;" : "=r"(rank));
    const int cluster = blockIdx.x / NCTA;
    const int gb0 = cluster * BC;

    // ---- load weight slices: local row lr = g*32+u <-> global row g*128 + rank*32 + u
    for (int i = tid; i < LROWS * HID; i += NTHREADS) {
        int lr = i / HID, k = i % HID;
        int g = lr >> 5, u = lr & 31;
        int gr = g * 128 + (int)rank * 32 + u;
        s.Whh0s[lr * PADH + k] = Whh0[gr * HID + k];
        s.Wih1s[lr * PADH + k] = Wih1[gr * HID + k];
        s.Whh1s[lr * PADH + k] = Whh1[gr * HID + k];
    }
    for (int lr = tid; lr < LROWS; lr += NTHREADS) {
        int g = lr >> 5, u = lr & 31;
        int gr = g * 128 + (int)rank * 32 + u;
        s.Wih0s[lr * 4 + 0] = Wih0[gr * 3 + 0];
        s.Wih0s[lr * 4 + 1] = Wih0[gr * 3 + 1];
        s.Wih0s[lr * 4 + 2] = Wih0[gr * 3 + 2];
        s.Wih0s[lr * 4 + 3] = 0.0f;
        s.b0s[lr] = bih0[gr] + bhh0[gr];
        s.b1s[lr] = bih1[gr] + bhh1[gr];
    }
    for (int i = tid; i < 2 * HID; i += NTHREADS) s.Wl[i] = Wl[i];
    if (tid < 2) s.bl[tid] = bl[tid];
    __syncthreads();
    cluster_sync_all();

    const int r    = tid >> 2;   // 0..127 : one gate row per thread
    const int b_of = tid & 3;    // batch within cluster

    int pw = 0;                  // ping-pong parity (identical across CTAs)
    float c0reg = 0.0f, c1reg = 0.0f, h0last = 0.0f, h1last = 0.0f;

    for (int w = 0; w < NWIN; w++) {
        // ---- build window inputs xin[t][b][f] for t=0..3
        if (tid < 64) {
            int t = tid >> 4, b = (tid >> 2) & 3, f = tid & 3;
            if (f < 3) {
                int gb = gb0 + b;
                float v;
                if (w == 0) {
                    v = traj[(gb * TT + t) * 3 + f];
                } else if (w < 4) {
                    if (t < 3) v = traj[(gb * TT + (w + t)) * 3 + f];
                    else v = (f == 0) ? traj[(gb * TT + (4 + w)) * 3 + 0]
                                      : s.winbuf[(b * 4 + 3) * 2 + (f - 1)];
                } else {
                    v = (f < 2) ? s.winbuf[(b * 4 + t) * 2 + f]
                                : traj[(gb * TT + (w + t)) * 3 + 0];
                }
                s.xin[(t * 4 + b) * 4 + f] = v;
            }
        }
        __syncthreads();

        // ---- s0: layer-0 gates at t=0 (x-only)
        {
            const float* x  = &s.xin[(0 * 4 + b_of) * 4];
            const float* wx = &s.Wih0s[r * 4];
            float a = s.b0s[r];
            a = fmaf(wx[0], x[0], fmaf(wx[1], x[1], fmaf(wx[2], x[2], a)));
            s.gates0[b_of * PADH + r] = a;
        }
        __syncthreads();
        if (tid >= 128 && tid < 256) {
            int t2 = tid - 128, ab = t2 >> 5, u = t2 & 31;
            h0last = act_one(s.gates0, c0reg, true, ab, u);
            push4(h0last, &s.h0buf[pw ^ 1][ab * PADH + (int)rank * 32 + u]);
        }
        cluster_sync_all();
        pw ^= 1;

        // ---- combined stages: produce h1[st] and h0[st+1] per sync
#pragma unroll
        for (int st = 0; st < 3; st++) {
            stage_gemv(s, s.h0buf[pw], s.h1buf[pw], r, b_of, st + 1, st > 0, true);
            __syncthreads();
            if (tid < 128) {
                int ab = tid >> 5, u = tid & 31;
                h1last = act_one(s.gates1, c1reg, st == 0, ab, u);
                push4(h1last, &s.h1buf[pw ^ 1][ab * PADH + (int)rank * 32 + u]);
            } else if (tid < 256) {
                int t2 = tid - 128, ab = t2 >> 5, u = t2 & 31;
                h0last = act_one(s.gates0, c0reg, false, ab, u);
                push4(h0last, &s.h0buf[pw ^ 1][ab * PADH + (int)rank * 32 + u]);
            }
            cluster_sync_all();
            pw ^= 1;
        }

        // ---- s4: last layer-1 step (t=3)
        stage_gemv(s, s.h0buf[pw], s.h1buf[pw], r, b_of, 0, true, false);
        __syncthreads();
        if (tid < 128) {
            int ab = tid >> 5, u = tid & 31;
            h1last = act_one(s.gates1, c1reg, false, ab, u);
            push4(h1last, &s.h1buf[pw ^ 1][ab * PADH + (int)rank * 32 + u]);
        }
        cluster_sync_all();
        pw ^= 1;

        // ---- head: pred[b][o] = Wl[o,:]·h1[b,:] + bl[o]  (8 warps, warp reduce)
        if (tid < 256) {
            int wid = tid >> 5, lane = tid & 31;
            int b = wid >> 1, o = wid & 1;
            const float4* wl4 = reinterpret_cast<const float4*>(&s.Wl[o * HID]);
            const float4* h4  = reinterpret_cast<const float4*>(&s.h1buf[pw][b * PADH]);
            float4 a = wl4[lane], hh = h4[lane];
            float p = a.x * hh.x + a.y * hh.y + a.z * hh.z + a.w * hh.w;
            p += __shfl_xor_sync(0xFFFFFFFFu, p, 16);
            p += __shfl_xor_sync(0xFFFFFFFFu, p, 8);
            p += __shfl_xor_sync(0xFFFFFFFFu, p, 4);
            p += __shfl_xor_sync(0xFFFFFFFFu, p, 2);
            p += __shfl_xor_sync(0xFFFFFFFFu, p, 1);
            if (lane == 0) s.pred[b * 2 + o] = p + s.bl[o];
        }
        __syncthreads();
        if (tid < 8) {
            int b = tid >> 1, o = tid & 1;
            int gb = gb0 + b;
            float base = (w < 4) ? traj[(gb * TT + 3 + w) * 3 + 1 + o]
                                 : s.winbuf[(b * 4 + 3) * 2 + o];
            float pn = base + s.pred[b * 2 + o];
            float t1 = s.winbuf[(b * 4 + 1) * 2 + o];
            float t2 = s.winbuf[(b * 4 + 2) * 2 + o];
            float t3 = s.winbuf[(b * 4 + 3) * 2 + o];
            s.winbuf[(b * 4 + 0) * 2 + o] = t1;
            s.winbuf[(b * 4 + 1) * 2 + o] = t2;
            s.winbuf[(b * 4 + 2) * 2 + o] = t3;
            s.winbuf[(b * 4 + 3) * 2 + o] = pn;
            if (rank == 0) out[(gb * NWIN + w) * 2 + o] = pn;
        }
        __syncthreads();
    }

    // ---- final hidden/cell states from owner-thread registers
    const int OFF_H = 128 * NWIN * 2;          // 64512
    const int OFF_C = OFF_H + 2 * 128 * HID;   // 97280
    if (tid < 128) {
        int b = tid >> 5, u = tid & 31;
        int j = (int)rank * 32 + u, gb = gb0 + b;
        out[OFF_H + 1 * 128 * HID + gb * HID + j] = h1last;
        out[OFF_C + 1 * 128 * HID + gb * HID + j] = c1reg;
    } else if (tid < 256) {
        int t2 = tid - 128, b = t2 >> 5, u = t2 & 31;
        int j = (int)rank * 32 + u, gb = gb0 + b;
        out[OFF_H + 0 * 128 * HID + gb * HID + j] = h0last;
        out[OFF_C + 0 * 128 * HID + gb * HID + j] = c0reg;
    }
}

extern "C" void kernel_launch(void* const* d_in, const int* in_sizes, int n_in,
                              void* d_out, int out_size) {
    const float* traj = (const float*)d_in[0];
    const float* Wih0 = (const float*)d_in[1];
    const float* Whh0 = (const float*)d_in[2];
    const float* bih0 = (const float*)d_in[3];
    const float* bhh0 = (const float*)d_in[4];
    const float* Wih1 = (const float*)d_in[5];
    const float* Whh1 = (const float*)d_in[6];
    const float* bih1 = (const float*)d_in[7];
    const float* bhh1 = (const float*)d_in[8];
    const float* Wl   = (const float*)d_in[9];
    const float* bl   = (const float*)d_in[10];
    float* out = (float*)d_out;

    int smem = (int)sizeof(Smem);
    cudaFuncSetAttribute(lstm_kernel, cudaFuncAttributeMaxDynamicSharedMemorySize, smem);
    lstm_kernel<<<128, NTHREADS, smem>>>(traj, Wih0, Whh0, bih0, bhh0,
                                         Wih1, Whh1, bih1, bhh1, Wl, bl, out);
}